// round 3
// baseline (speedup 1.0000x reference)
#include <cuda_runtime.h>
#include <cuda_bf16.h>
#include <math.h>

#define D_MODEL 1024
#define T_SEQ   2048
#define B_BATCH 2
#define H_HEADS 16
#define DKH     64
#define M_ROWS  (B_BATCH * T_SEQ)   // 4096

// Scratch (allocation-free rule: __device__ globals)
__device__ float g_q[(size_t)M_ROWS * D_MODEL];
__device__ float g_k[(size_t)M_ROWS * D_MODEL];
__device__ float g_v[(size_t)M_ROWS * D_MODEL];
__device__ float g_att[(size_t)M_ROWS * D_MODEL];

// ---------------------------------------------------------------------------
// GEMM: C[M,N] = A[M,K] @ W[N,K]^T + bias[N]
// 128x128 tile, BK=8, 256 threads, 8x8 per thread.
// ---------------------------------------------------------------------------
__global__ __launch_bounds__(256) void gemm_bias_kernel(
    const float* __restrict__ A,
    const float* __restrict__ W,
    const float* __restrict__ bias,
    float* __restrict__ C,
    int M, int N, int K)
{
    __shared__ float As[8][128];   // As[k][m]
    __shared__ float Bs[8][128];   // Bs[k][n]

    const int tid = threadIdx.x;
    const int tx  = tid & 15;
    const int ty  = tid >> 4;
    const int m0  = blockIdx.y * 128;
    const int n0  = blockIdx.x * 128;

    const int lr = tid >> 1;          // 0..127
    const int lk = (tid & 1) * 4;     // 0 or 4

    const float* Ap = A + (size_t)(m0 + lr) * K + lk;
    const float* Wp = W + (size_t)(n0 + lr) * K + lk;

    float acc[8][8];
#pragma unroll
    for (int i = 0; i < 8; i++)
#pragma unroll
        for (int j = 0; j < 8; j++) acc[i][j] = 0.f;

    for (int k0 = 0; k0 < K; k0 += 8) {
        float4 av = *(const float4*)(Ap + k0);
        float4 wv = *(const float4*)(Wp + k0);
        __syncthreads();
        As[lk + 0][lr] = av.x; As[lk + 1][lr] = av.y;
        As[lk + 2][lr] = av.z; As[lk + 3][lr] = av.w;
        Bs[lk + 0][lr] = wv.x; Bs[lk + 1][lr] = wv.y;
        Bs[lk + 2][lr] = wv.z; Bs[lk + 3][lr] = wv.w;
        __syncthreads();
#pragma unroll
        for (int k = 0; k < 8; k++) {
            float a[8], b[8];
            *(float4*)(a)     = *(const float4*)(&As[k][ty * 4]);
            *(float4*)(a + 4) = *(const float4*)(&As[k][64 + ty * 4]);
            *(float4*)(b)     = *(const float4*)(&Bs[k][tx * 4]);
            *(float4*)(b + 4) = *(const float4*)(&Bs[k][64 + tx * 4]);
#pragma unroll
            for (int i = 0; i < 8; i++)
#pragma unroll
                for (int j = 0; j < 8; j++)
                    acc[i][j] += a[i] * b[j];
        }
    }

    float bf[8];
    *(float4*)(bf)     = *(const float4*)(bias + n0 + tx * 4);
    *(float4*)(bf + 4) = *(const float4*)(bias + n0 + 64 + tx * 4);

#pragma unroll
    for (int i = 0; i < 8; i++) {
        int row = m0 + ((i < 4) ? (ty * 4 + i) : (64 + ty * 4 + (i - 4)));
        float* Cp = C + (size_t)row * N + n0;
        float4 v0 = make_float4(acc[i][0] + bf[0], acc[i][1] + bf[1],
                                acc[i][2] + bf[2], acc[i][3] + bf[3]);
        float4 v1 = make_float4(acc[i][4] + bf[4], acc[i][5] + bf[5],
                                acc[i][6] + bf[6], acc[i][7] + bf[7]);
        *(float4*)(Cp + tx * 4)      = v0;
        *(float4*)(Cp + 64 + tx * 4) = v1;
    }
}

// ---------------------------------------------------------------------------
// Fused flash attention (fp32, key-padding mask as int32).
// Grid: (T/64, B*H). Block: 256 threads (16x16, 4x4 micro-tile).
// smem: QT/KT/PT transposed (stride 65), V natural (stride 64), mask floats.
// ---------------------------------------------------------------------------
#define AT_SMEM_FLOATS (3 * 64 * 65 + 64 * 64 + 64)
#define AT_SMEM_BYTES  (AT_SMEM_FLOATS * 4)

__global__ __launch_bounds__(256) void attn_kernel(const int* __restrict__ mask)
{
    extern __shared__ float sm[];
    float* QT = sm;                 // [64 d][65] : QT[d*65 + r]
    float* KT = QT + 64 * 65;       // [64 d][65] : KT[d*65 + c]
    float* PT = KT + 64 * 65;       // [64 s][65] : PT[s*65 + r]
    float* Vs = PT + 64 * 65;       // [64 s][64] : Vs[s*64 + n]
    float* Mf = Vs + 64 * 64;       // [64]

    const int tid = threadIdx.x;
    const int tx  = tid & 15;
    const int ty  = tid >> 4;
    const int qt  = blockIdx.x;
    const int bh  = blockIdx.y;
    const int b   = bh >> 4;        // H=16
    const int h   = bh & 15;

    const float* Qg = g_q + (size_t)(b * T_SEQ + qt * 64) * D_MODEL + h * 64;
    const float* Kg = g_k + (size_t)(b * T_SEQ) * D_MODEL + h * 64;
    const float* Vg = g_v + (size_t)(b * T_SEQ) * D_MODEL + h * 64;
    const int* mb = mask + b * T_SEQ;

    // Load Q tile transposed (once per block)
#pragma unroll
    for (int it = 0; it < 4; it++) {
        int v  = tid + it * 256;      // 0..1023 float4 slots
        int r  = v >> 4;              // 0..63
        int dg = (v & 15) << 2;       // 0..60
        float4 q = *(const float4*)(Qg + (size_t)r * D_MODEL + dg);
        QT[(dg + 0) * 65 + r] = q.x;
        QT[(dg + 1) * 65 + r] = q.y;
        QT[(dg + 2) * 65 + r] = q.z;
        QT[(dg + 3) * 65 + r] = q.w;
    }

    float O[4][4];
    float m_r[4], l_r[4];
#pragma unroll
    for (int i = 0; i < 4; i++) {
        m_r[i] = -1e30f;
        l_r[i] = 0.f;
#pragma unroll
        for (int j = 0; j < 4; j++) O[i][j] = 0.f;
    }

    for (int s0 = 0; s0 < T_SEQ; s0 += 64) {
        __syncthreads();   // previous PV phase done with Vs/PT

        // Load K tile transposed + V tile natural
#pragma unroll
        for (int it = 0; it < 4; it++) {
            int v  = tid + it * 256;
            int r  = v >> 4;
            int dg = (v & 15) << 2;
            float4 kv = *(const float4*)(Kg + (size_t)(s0 + r) * D_MODEL + dg);
            KT[(dg + 0) * 65 + r] = kv.x;
            KT[(dg + 1) * 65 + r] = kv.y;
            KT[(dg + 2) * 65 + r] = kv.z;
            KT[(dg + 3) * 65 + r] = kv.w;
            float4 vv = *(const float4*)(Vg + (size_t)(s0 + r) * D_MODEL + dg);
            *(float4*)(&Vs[r * 64 + dg]) = vv;
        }
        if (tid < 64) Mf[tid] = (mb[s0 + tid] != 0) ? 1.0f : 0.0f;
        __syncthreads();

        // S = Q K^T (4x4 per thread)
        float sreg[4][4];
#pragma unroll
        for (int i = 0; i < 4; i++)
#pragma unroll
            for (int j = 0; j < 4; j++) sreg[i][j] = 0.f;

#pragma unroll 8
        for (int d = 0; d < 64; d++) {
            float q0 = QT[d * 65 + 4 * ty + 0];
            float q1 = QT[d * 65 + 4 * ty + 1];
            float q2 = QT[d * 65 + 4 * ty + 2];
            float q3 = QT[d * 65 + 4 * ty + 3];
            float k0 = KT[d * 65 + 4 * tx + 0];
            float k1 = KT[d * 65 + 4 * tx + 1];
            float k2 = KT[d * 65 + 4 * tx + 2];
            float k3 = KT[d * 65 + 4 * tx + 3];
            sreg[0][0] += q0 * k0; sreg[0][1] += q0 * k1; sreg[0][2] += q0 * k2; sreg[0][3] += q0 * k3;
            sreg[1][0] += q1 * k0; sreg[1][1] += q1 * k1; sreg[1][2] += q1 * k2; sreg[1][3] += q1 * k3;
            sreg[2][0] += q2 * k0; sreg[2][1] += q2 * k1; sreg[2][2] += q2 * k2; sreg[2][3] += q2 * k3;
            sreg[3][0] += q3 * k0; sreg[3][1] += q3 * k1; sreg[3][2] += q3 * k2; sreg[3][3] += q3 * k3;
        }

        float mk[4];
#pragma unroll
        for (int j = 0; j < 4; j++) mk[j] = Mf[4 * tx + j];

        const float SCALE = 0.125f;   // 1/sqrt(64)

        // online softmax per owned row
#pragma unroll
        for (int i = 0; i < 4; i++) {
            float mx = -1e30f;
#pragma unroll
            for (int j = 0; j < 4; j++) {
                float sv = sreg[i][j] * SCALE;
                sv = (mk[j] > 0.f) ? sv : -1e30f;
                sreg[i][j] = sv;
                mx = fmaxf(mx, sv);
            }
#pragma unroll
            for (int o = 8; o >= 1; o >>= 1)
                mx = fmaxf(mx, __shfl_xor_sync(0xffffffffu, mx, o));

            float mnew = fmaxf(m_r[i], mx);
            float corr = __expf(m_r[i] - mnew);
            float rs = 0.f;
#pragma unroll
            for (int j = 0; j < 4; j++) {
                float p = __expf(sreg[i][j] - mnew) * mk[j];
                PT[(4 * tx + j) * 65 + 4 * ty + i] = p;
                rs += p;
            }
#pragma unroll
            for (int o = 8; o >= 1; o >>= 1)
                rs += __shfl_xor_sync(0xffffffffu, rs, o);

            l_r[i] = l_r[i] * corr + rs;
            m_r[i] = mnew;
#pragma unroll
            for (int j = 0; j < 4; j++) O[i][j] *= corr;
        }
        __syncthreads();

        // O += P @ V
#pragma unroll 8
        for (int s = 0; s < 64; s++) {
            float4 vv = *(const float4*)(&Vs[s * 64 + 4 * tx]);
            float p0 = PT[s * 65 + 4 * ty + 0];
            float p1 = PT[s * 65 + 4 * ty + 1];
            float p2 = PT[s * 65 + 4 * ty + 2];
            float p3 = PT[s * 65 + 4 * ty + 3];
            O[0][0] += p0 * vv.x; O[0][1] += p0 * vv.y; O[0][2] += p0 * vv.z; O[0][3] += p0 * vv.w;
            O[1][0] += p1 * vv.x; O[1][1] += p1 * vv.y; O[1][2] += p1 * vv.z; O[1][3] += p1 * vv.w;
            O[2][0] += p2 * vv.x; O[2][1] += p2 * vv.y; O[2][2] += p2 * vv.z; O[2][3] += p2 * vv.w;
            O[3][0] += p3 * vv.x; O[3][1] += p3 * vv.y; O[3][2] += p3 * vv.z; O[3][3] += p3 * vv.w;
        }
    }

    // finalize and store to g_att (head-concat layout)
#pragma unroll
    for (int i = 0; i < 4; i++) {
        float inv = (l_r[i] > 0.f) ? (1.0f / l_r[i]) : 0.f;
        size_t row = (size_t)(b * T_SEQ + qt * 64 + 4 * ty + i);
        float4 o4 = make_float4(O[i][0] * inv, O[i][1] * inv,
                                O[i][2] * inv, O[i][3] * inv);
        *(float4*)(g_att + row * D_MODEL + h * 64 + 4 * tx) = o4;
    }
}

// ---------------------------------------------------------------------------
extern "C" void kernel_launch(void* const* d_in, const int* in_sizes, int n_in,
                              void* d_out, int out_size)
{
    const float* query = (const float*)d_in[0];
    const float* key   = (const float*)d_in[1];
    const float* value = (const float*)d_in[2];
    const int*   mask  = (const int*)d_in[3];
    const float* Wq = (const float*)d_in[4];
    const float* bq = (const float*)d_in[5];
    const float* Wk = (const float*)d_in[6];
    const float* bk = (const float*)d_in[7];
    const float* Wv = (const float*)d_in[8];
    const float* bv = (const float*)d_in[9];
    const float* Wo = (const float*)d_in[10];
    const float* bo = (const float*)d_in[11];
    float* out = (float*)d_out;

    float *gq, *gk, *gv, *ga;
    cudaGetSymbolAddress((void**)&gq, g_q);
    cudaGetSymbolAddress((void**)&gk, g_k);
    cudaGetSymbolAddress((void**)&gv, g_v);
    cudaGetSymbolAddress((void**)&ga, g_att);

    cudaFuncSetAttribute(attn_kernel,
                         cudaFuncAttributeMaxDynamicSharedMemorySize,
                         AT_SMEM_BYTES);

    dim3 ggrid(D_MODEL / 128, M_ROWS / 128);   // (8, 32)
    gemm_bias_kernel<<<ggrid, 256>>>(query, Wq, bq, gq, M_ROWS, D_MODEL, D_MODEL);
    gemm_bias_kernel<<<ggrid, 256>>>(key,   Wk, bk, gk, M_ROWS, D_MODEL, D_MODEL);
    gemm_bias_kernel<<<ggrid, 256>>>(value, Wv, bv, gv, M_ROWS, D_MODEL, D_MODEL);

    dim3 agrid(T_SEQ / 64, B_BATCH * H_HEADS); // (32, 32)
    attn_kernel<<<agrid, 256, AT_SMEM_BYTES>>>(mask);

    gemm_bias_kernel<<<ggrid, 256>>>(ga, Wo, bo, out, M_ROWS, D_MODEL, D_MODEL);
}

// round 5
// speedup vs baseline: 1.2843x; 1.2843x over previous
#include <cuda_runtime.h>
#include <cuda_bf16.h>
#include <math.h>
#include <stdint.h>

#define D_MODEL 1024
#define T_SEQ   2048
#define B_BATCH 2
#define H_HEADS 16
#define M_ROWS  (B_BATCH * T_SEQ)   // 4096

// ---------------- scratch (__device__ globals; no allocations) ----------------
__device__ float g_q[(size_t)M_ROWS * D_MODEL];
__device__ float g_k[(size_t)M_ROWS * D_MODEL];
__device__ float g_v[(size_t)M_ROWS * D_MODEL];
__device__ float g_att[(size_t)M_ROWS * D_MODEL];
__device__ __nv_bfloat16 g_ah[(size_t)M_ROWS * D_MODEL];   // activation hi
__device__ __nv_bfloat16 g_al[(size_t)M_ROWS * D_MODEL];   // activation lo
__device__ __nv_bfloat16 g_wh[(size_t)D_MODEL * D_MODEL];  // weight hi
__device__ __nv_bfloat16 g_wl[(size_t)D_MODEL * D_MODEL];  // weight lo

// ---------------- helpers ----------------
__device__ __forceinline__ uint32_t smem_u32(const void* p) {
    uint32_t a;
    asm("{ .reg .u64 t; cvta.to.shared.u64 t, %1; cvt.u32.u64 %0, t; }" : "=r"(a) : "l"(p));
    return a;
}
__device__ __forceinline__ void ldsm_x4(uint32_t (&r)[4], uint32_t addr) {
    asm volatile("ldmatrix.sync.aligned.m8n8.x4.shared.b16 {%0,%1,%2,%3}, [%4];"
        : "=r"(r[0]), "=r"(r[1]), "=r"(r[2]), "=r"(r[3]) : "r"(addr));
}
__device__ __forceinline__ void ldsm_x2(uint32_t (&r)[2], uint32_t addr) {
    asm volatile("ldmatrix.sync.aligned.m8n8.x2.shared.b16 {%0,%1}, [%2];"
        : "=r"(r[0]), "=r"(r[1]) : "r"(addr));
}
__device__ __forceinline__ void mma16816(float (&d)[4], const uint32_t (&a)[4],
                                         const uint32_t (&b)[2]) {
    asm volatile("mma.sync.aligned.m16n8k16.row.col.f32.bf16.bf16.f32 "
        "{%0,%1,%2,%3}, {%4,%5,%6,%7}, {%8,%9}, {%0,%1,%2,%3};"
        : "+f"(d[0]), "+f"(d[1]), "+f"(d[2]), "+f"(d[3])
        : "r"(a[0]), "r"(a[1]), "r"(a[2]), "r"(a[3]), "r"(b[0]), "r"(b[1]));
}

// ---------------- fp32 -> bf16 hi/lo split ----------------
__global__ __launch_bounds__(256) void conv_split_kernel(
    const float* __restrict__ x, __nv_bfloat16* __restrict__ hi,
    __nv_bfloat16* __restrict__ lo, int n4)
{
    int i = blockIdx.x * 256 + threadIdx.x;
    if (i >= n4) return;
    float4 v = ((const float4*)x)[i];
    __nv_bfloat16 h0 = __float2bfloat16(v.x), h1 = __float2bfloat16(v.y);
    __nv_bfloat16 h2 = __float2bfloat16(v.z), h3 = __float2bfloat16(v.w);
    __nv_bfloat16 l0 = __float2bfloat16(v.x - __bfloat162float(h0));
    __nv_bfloat16 l1 = __float2bfloat16(v.y - __bfloat162float(h1));
    __nv_bfloat16 l2 = __float2bfloat16(v.z - __bfloat162float(h2));
    __nv_bfloat16 l3 = __float2bfloat16(v.w - __bfloat162float(h3));
    ((__nv_bfloat162*)hi)[2 * i]     = __nv_bfloat162(h0, h1);
    ((__nv_bfloat162*)hi)[2 * i + 1] = __nv_bfloat162(h2, h3);
    ((__nv_bfloat162*)lo)[2 * i]     = __nv_bfloat162(l0, l1);
    ((__nv_bfloat162*)lo)[2 * i + 1] = __nv_bfloat162(l2, l3);
}

// ---------------- mma.sync GEMM: C[4096,1024] = A @ W^T + bias ----------------
// CTA tile 128x128, BK=32, 8 warps (2m x 4n), warp tile 64x32.
// smem rows: 80B stride (5 x 16B) -> ldmatrix conflict-free without swizzle.
#define G_STRIDE_B   80                       // bytes per smem row
#define G_TILE_B     (128 * G_STRIDE_B)       // 10240 B per tile
#define G_STAGE_B    (4 * G_TILE_B)           // Ah,Al,Wh,Wl = 40960 B
#define G_SMEM_B     (2 * G_STAGE_B)          // 81920 B
#define G_NC         (D_MODEL / 32)           // 32 k-chunks

__global__ __launch_bounds__(256) void gemm_mma_kernel(
    const __nv_bfloat16* __restrict__ Ah, const __nv_bfloat16* __restrict__ Al,
    const __nv_bfloat16* __restrict__ Wh, const __nv_bfloat16* __restrict__ Wl,
    const float* __restrict__ bias, float* __restrict__ C)
{
    extern __shared__ char smem[];
    const uint32_t sbase = smem_u32(smem);
    const int tid  = threadIdx.x;
    const int wid  = tid >> 5;
    const int lane = tid & 31;
    const int wm   = wid >> 2;     // 0..1
    const int wn   = wid & 3;      // 0..3
    const int m0 = blockIdx.y * 128;
    const int n0 = blockIdx.x * 128;

    const __nv_bfloat16* base[4] = {
        Ah + (size_t)m0 * D_MODEL, Al + (size_t)m0 * D_MODEL,
        Wh + (size_t)n0 * D_MODEL, Wl + (size_t)n0 * D_MODEL
    };

    float acc[4][4][4];
#pragma unroll
    for (int i = 0; i < 4; i++)
#pragma unroll
        for (int j = 0; j < 4; j++)
#pragma unroll
            for (int k = 0; k < 4; k++) acc[i][j][k] = 0.f;

    uint4 ldreg[8];
    auto ldg_chunk = [&](int c) {
#pragma unroll
        for (int it = 0; it < 8; it++) {
            int g   = tid + it * 256;       // 0..2047
            int p   = g >> 9;               // tile 0..3
            int idx = g & 511;
            int row = idx >> 2;             // 0..127
            int ch  = idx & 3;              // 16B chunk in 64B row
            ldreg[it] = *(const uint4*)(base[p] + (size_t)row * D_MODEL + c * 32 + ch * 8);
        }
    };
    auto sts_chunk = [&](int s) {
        char* dst = smem + s * G_STAGE_B;
#pragma unroll
        for (int it = 0; it < 8; it++) {
            int g   = tid + it * 256;
            int p   = g >> 9;
            int idx = g & 511;
            int row = idx >> 2;
            int ch  = idx & 3;
            *(uint4*)(dst + p * G_TILE_B + row * G_STRIDE_B + ch * 16) = ldreg[it];
        }
    };

    // per-lane ldmatrix address components
    const int a_row = wm * 64 + (lane & 7) + ((lane >> 3) & 1) * 8;  // + mi*16
    const int a_cho = (lane >> 4) & 1;                               // + 2*ks
    const int b_row = wn * 32 + (lane & 7);                          // + ni*8
    const int b_cho = (lane >> 3) & 1;                               // + 2*ks

    auto compute = [&](int s) {
        const uint32_t st  = sbase + s * G_STAGE_B;
        const uint32_t aHb = st + a_row * G_STRIDE_B + a_cho * 16;
        const uint32_t bHb = st + 2 * G_TILE_B + b_row * G_STRIDE_B + b_cho * 16;
#pragma unroll
        for (int ks = 0; ks < 2; ks++) {
            uint32_t aks = aHb + ks * 32;
            uint32_t bks = bHb + ks * 32;
            uint32_t aH[4][4], aL[4][4];
#pragma unroll
            for (int mi = 0; mi < 4; mi++) {
                ldsm_x4(aH[mi], aks + mi * (16 * G_STRIDE_B));
                ldsm_x4(aL[mi], aks + G_TILE_B + mi * (16 * G_STRIDE_B));
            }
#pragma unroll
            for (int ni = 0; ni < 4; ni++) {
                uint32_t bH[2], bL[2];
                ldsm_x2(bH, bks + ni * (8 * G_STRIDE_B));
                ldsm_x2(bL, bks + G_TILE_B + ni * (8 * G_STRIDE_B));
#pragma unroll
                for (int mi = 0; mi < 4; mi++) {
                    mma16816(acc[mi][ni], aH[mi], bH);
                    mma16816(acc[mi][ni], aH[mi], bL);
                    mma16816(acc[mi][ni], aL[mi], bH);
                }
            }
        }
    };

    // pipeline
    ldg_chunk(0);
    sts_chunk(0);
    __syncthreads();
    for (int c = 0; c < G_NC; c++) {
        if (c + 1 < G_NC) ldg_chunk(c + 1);
        compute(c & 1);
        __syncthreads();
        if (c + 1 < G_NC) {
            sts_chunk((c + 1) & 1);
            __syncthreads();
        }
    }

    // epilogue: direct gmem stores + bias
    const int mb = m0 + wm * 64;
    const int nb = n0 + wn * 32;
    const int rl = lane >> 2;            // 0..7
    const int cl = 2 * (lane & 3);       // 0,2,4,6
#pragma unroll
    for (int ni = 0; ni < 4; ni++) {
        int cc = nb + ni * 8 + cl;
        float2 bv = *(const float2*)(bias + cc);
#pragma unroll
        for (int mi = 0; mi < 4; mi++) {
            int r0 = mb + mi * 16 + rl;
            float2 v0 = make_float2(acc[mi][ni][0] + bv.x, acc[mi][ni][1] + bv.y);
            float2 v1 = make_float2(acc[mi][ni][2] + bv.x, acc[mi][ni][3] + bv.y);
            *(float2*)(C + (size_t)r0 * D_MODEL + cc)       = v0;
            *(float2*)(C + (size_t)(r0 + 8) * D_MODEL + cc) = v1;
        }
    }
}

// ---------------------------------------------------------------------------
// Fused flash attention (fp32, key-padding mask as int32). Unchanged (passing).
// ---------------------------------------------------------------------------
#define AT_SMEM_FLOATS (3 * 64 * 65 + 64 * 64 + 64)
#define AT_SMEM_BYTES  (AT_SMEM_FLOATS * 4)

__global__ __launch_bounds__(256) void attn_kernel(const int* __restrict__ mask)
{
    extern __shared__ float sm[];
    float* QT = sm;
    float* KT = QT + 64 * 65;
    float* PT = KT + 64 * 65;
    float* Vs = PT + 64 * 65;
    float* Mf = Vs + 64 * 64;

    const int tid = threadIdx.x;
    const int tx  = tid & 15;
    const int ty  = tid >> 4;
    const int qt  = blockIdx.x;
    const int bh  = blockIdx.y;
    const int b   = bh >> 4;
    const int h   = bh & 15;

    const float* Qg = g_q + (size_t)(b * T_SEQ + qt * 64) * D_MODEL + h * 64;
    const float* Kg = g_k + (size_t)(b * T_SEQ) * D_MODEL + h * 64;
    const float* Vg = g_v + (size_t)(b * T_SEQ) * D_MODEL + h * 64;
    const int* mb = mask + b * T_SEQ;

#pragma unroll
    for (int it = 0; it < 4; it++) {
        int v  = tid + it * 256;
        int r  = v >> 4;
        int dg = (v & 15) << 2;
        float4 q = *(const float4*)(Qg + (size_t)r * D_MODEL + dg);
        QT[(dg + 0) * 65 + r] = q.x;
        QT[(dg + 1) * 65 + r] = q.y;
        QT[(dg + 2) * 65 + r] = q.z;
        QT[(dg + 3) * 65 + r] = q.w;
    }

    float O[4][4];
    float m_r[4], l_r[4];
#pragma unroll
    for (int i = 0; i < 4; i++) {
        m_r[i] = -1e30f; l_r[i] = 0.f;
#pragma unroll
        for (int j = 0; j < 4; j++) O[i][j] = 0.f;
    }

    for (int s0 = 0; s0 < T_SEQ; s0 += 64) {
        __syncthreads();
#pragma unroll
        for (int it = 0; it < 4; it++) {
            int v  = tid + it * 256;
            int r  = v >> 4;
            int dg = (v & 15) << 2;
            float4 kv = *(const float4*)(Kg + (size_t)(s0 + r) * D_MODEL + dg);
            KT[(dg + 0) * 65 + r] = kv.x;
            KT[(dg + 1) * 65 + r] = kv.y;
            KT[(dg + 2) * 65 + r] = kv.z;
            KT[(dg + 3) * 65 + r] = kv.w;
            float4 vv = *(const float4*)(Vg + (size_t)(s0 + r) * D_MODEL + dg);
            *(float4*)(&Vs[r * 64 + dg]) = vv;
        }
        if (tid < 64) Mf[tid] = (mb[s0 + tid] != 0) ? 1.0f : 0.0f;
        __syncthreads();

        float sreg[4][4];
#pragma unroll
        for (int i = 0; i < 4; i++)
#pragma unroll
            for (int j = 0; j < 4; j++) sreg[i][j] = 0.f;

#pragma unroll 8
        for (int d = 0; d < 64; d++) {
            float q0 = QT[d * 65 + 4 * ty + 0];
            float q1 = QT[d * 65 + 4 * ty + 1];
            float q2 = QT[d * 65 + 4 * ty + 2];
            float q3 = QT[d * 65 + 4 * ty + 3];
            float k0 = KT[d * 65 + 4 * tx + 0];
            float k1 = KT[d * 65 + 4 * tx + 1];
            float k2 = KT[d * 65 + 4 * tx + 2];
            float k3 = KT[d * 65 + 4 * tx + 3];
            sreg[0][0] += q0 * k0; sreg[0][1] += q0 * k1; sreg[0][2] += q0 * k2; sreg[0][3] += q0 * k3;
            sreg[1][0] += q1 * k0; sreg[1][1] += q1 * k1; sreg[1][2] += q1 * k2; sreg[1][3] += q1 * k3;
            sreg[2][0] += q2 * k0; sreg[2][1] += q2 * k1; sreg[2][2] += q2 * k2; sreg[2][3] += q2 * k3;
            sreg[3][0] += q3 * k0; sreg[3][1] += q3 * k1; sreg[3][2] += q3 * k2; sreg[3][3] += q3 * k3;
        }

        float mk[4];
#pragma unroll
        for (int j = 0; j < 4; j++) mk[j] = Mf[4 * tx + j];

        const float SCALE = 0.125f;
#pragma unroll
        for (int i = 0; i < 4; i++) {
            float mx = -1e30f;
#pragma unroll
            for (int j = 0; j < 4; j++) {
                float sv = sreg[i][j] * SCALE;
                sv = (mk[j] > 0.f) ? sv : -1e30f;
                sreg[i][j] = sv;
                mx = fmaxf(mx, sv);
            }
#pragma unroll
            for (int o = 8; o >= 1; o >>= 1)
                mx = fmaxf(mx, __shfl_xor_sync(0xffffffffu, mx, o));

            float mnew = fmaxf(m_r[i], mx);
            float corr = __expf(m_r[i] - mnew);
            float rs = 0.f;
#pragma unroll
            for (int j = 0; j < 4; j++) {
                float p = __expf(sreg[i][j] - mnew) * mk[j];
                PT[(4 * tx + j) * 65 + 4 * ty + i] = p;
                rs += p;
            }
#pragma unroll
            for (int o = 8; o >= 1; o >>= 1)
                rs += __shfl_xor_sync(0xffffffffu, rs, o);

            l_r[i] = l_r[i] * corr + rs;
            m_r[i] = mnew;
#pragma unroll
            for (int j = 0; j < 4; j++) O[i][j] *= corr;
        }
        __syncthreads();

#pragma unroll 8
        for (int s = 0; s < 64; s++) {
            float4 vv = *(const float4*)(&Vs[s * 64 + 4 * tx]);
            float p0 = PT[s * 65 + 4 * ty + 0];
            float p1 = PT[s * 65 + 4 * ty + 1];
            float p2 = PT[s * 65 + 4 * ty + 2];
            float p3 = PT[s * 65 + 4 * ty + 3];
            O[0][0] += p0 * vv.x; O[0][1] += p0 * vv.y; O[0][2] += p0 * vv.z; O[0][3] += p0 * vv.w;
            O[1][0] += p1 * vv.x; O[1][1] += p1 * vv.y; O[1][2] += p1 * vv.z; O[1][3] += p1 * vv.w;
            O[2][0] += p2 * vv.x; O[2][1] += p2 * vv.y; O[2][2] += p2 * vv.z; O[2][3] += p2 * vv.w;
            O[3][0] += p3 * vv.x; O[3][1] += p3 * vv.y; O[3][2] += p3 * vv.z; O[3][3] += p3 * vv.w;
        }
    }

#pragma unroll
    for (int i = 0; i < 4; i++) {
        float inv = (l_r[i] > 0.f) ? (1.0f / l_r[i]) : 0.f;
        size_t row = (size_t)(b * T_SEQ + qt * 64 + 4 * ty + i);
        float4 o4 = make_float4(O[i][0] * inv, O[i][1] * inv,
                                O[i][2] * inv, O[i][3] * inv);
        *(float4*)(g_att + row * D_MODEL + h * 64 + 4 * tx) = o4;
    }
}

// ---------------------------------------------------------------------------
extern "C" void kernel_launch(void* const* d_in, const int* in_sizes, int n_in,
                              void* d_out, int out_size)
{
    const float* query = (const float*)d_in[0];
    const float* key   = (const float*)d_in[1];
    const float* value = (const float*)d_in[2];
    const int*   mask  = (const int*)d_in[3];
    const float* Wq = (const float*)d_in[4];
    const float* bq = (const float*)d_in[5];
    const float* Wk = (const float*)d_in[6];
    const float* bk = (const float*)d_in[7];
    const float* Wv = (const float*)d_in[8];
    const float* bv = (const float*)d_in[9];
    const float* Wo = (const float*)d_in[10];
    const float* bo = (const float*)d_in[11];
    float* out = (float*)d_out;

    float *gq, *gk, *gv, *ga;
    __nv_bfloat16 *ah, *al, *wh, *wl;
    cudaGetSymbolAddress((void**)&gq, g_q);
    cudaGetSymbolAddress((void**)&gk, g_k);
    cudaGetSymbolAddress((void**)&gv, g_v);
    cudaGetSymbolAddress((void**)&ga, g_att);
    cudaGetSymbolAddress((void**)&ah, g_ah);
    cudaGetSymbolAddress((void**)&al, g_al);
    cudaGetSymbolAddress((void**)&wh, g_wh);
    cudaGetSymbolAddress((void**)&wl, g_wl);

    cudaFuncSetAttribute(attn_kernel, cudaFuncAttributeMaxDynamicSharedMemorySize, AT_SMEM_BYTES);
    cudaFuncSetAttribute(gemm_mma_kernel, cudaFuncAttributeMaxDynamicSharedMemorySize, G_SMEM_B);

    const int nact4 = M_ROWS * D_MODEL / 4;    // 1M float4
    const int nw4   = D_MODEL * D_MODEL / 4;   // 256K float4
    dim3 cga(nact4 / 256), cgw(nw4 / 256);
    dim3 ggrid(D_MODEL / 128, M_ROWS / 128);   // (8, 32)

    // Q projection
    conv_split_kernel<<<cga, 256>>>(query, ah, al, nact4);
    conv_split_kernel<<<cgw, 256>>>(Wq, wh, wl, nw4);
    gemm_mma_kernel<<<ggrid, 256, G_SMEM_B>>>(ah, al, wh, wl, bq, gq);
    // K projection
    conv_split_kernel<<<cga, 256>>>(key, ah, al, nact4);
    conv_split_kernel<<<cgw, 256>>>(Wk, wh, wl, nw4);
    gemm_mma_kernel<<<ggrid, 256, G_SMEM_B>>>(ah, al, wh, wl, bk, gk);
    // V projection
    conv_split_kernel<<<cga, 256>>>(value, ah, al, nact4);
    conv_split_kernel<<<cgw, 256>>>(Wv, wh, wl, nw4);
    gemm_mma_kernel<<<ggrid, 256, G_SMEM_B>>>(ah, al, wh, wl, bv, gv);

    // attention
    dim3 agrid(T_SEQ / 64, B_BATCH * H_HEADS);
    attn_kernel<<<agrid, 256, AT_SMEM_BYTES>>>(mask);

    // output projection
    conv_split_kernel<<<cga, 256>>>(ga, ah, al, nact4);
    conv_split_kernel<<<cgw, 256>>>(Wo, wh, wl, nw4);
    gemm_mma_kernel<<<ggrid, 256, G_SMEM_B>>>(ah, al, wh, wl, bo, out);
}

// round 6
// speedup vs baseline: 2.3828x; 1.8553x over previous
#include <cuda_runtime.h>
#include <cuda_bf16.h>
#include <math.h>
#include <stdint.h>

#define D_MODEL 1024
#define T_SEQ   2048
#define B_BATCH 2
#define H_HEADS 16
#define M_ROWS  (B_BATCH * T_SEQ)   // 4096

// ---------------- scratch (__device__ globals; no allocations) ----------------
__device__ float g_q[(size_t)M_ROWS * D_MODEL];
__device__ float g_k[(size_t)M_ROWS * D_MODEL];
__device__ float g_v[(size_t)M_ROWS * D_MODEL];
__device__ __nv_bfloat16 g_ah[(size_t)M_ROWS * D_MODEL];   // activation hi
__device__ __nv_bfloat16 g_al[(size_t)M_ROWS * D_MODEL];   // activation lo
__device__ __nv_bfloat16 g_wh[(size_t)D_MODEL * D_MODEL];  // weight hi
__device__ __nv_bfloat16 g_wl[(size_t)D_MODEL * D_MODEL];  // weight lo

// ---------------- helpers ----------------
__device__ __forceinline__ uint32_t smem_u32(const void* p) {
    uint32_t a;
    asm("{ .reg .u64 t; cvta.to.shared.u64 t, %1; cvt.u32.u64 %0, t; }" : "=r"(a) : "l"(p));
    return a;
}
__device__ __forceinline__ void ldsm_x4(uint32_t (&r)[4], uint32_t addr) {
    asm volatile("ldmatrix.sync.aligned.m8n8.x4.shared.b16 {%0,%1,%2,%3}, [%4];"
        : "=r"(r[0]), "=r"(r[1]), "=r"(r[2]), "=r"(r[3]) : "r"(addr));
}
__device__ __forceinline__ void ldsm_x4t(uint32_t (&r)[4], uint32_t addr) {
    asm volatile("ldmatrix.sync.aligned.m8n8.x4.trans.shared.b16 {%0,%1,%2,%3}, [%4];"
        : "=r"(r[0]), "=r"(r[1]), "=r"(r[2]), "=r"(r[3]) : "r"(addr));
}
__device__ __forceinline__ void ldsm_x2(uint32_t (&r)[2], uint32_t addr) {
    asm volatile("ldmatrix.sync.aligned.m8n8.x2.shared.b16 {%0,%1}, [%2];"
        : "=r"(r[0]), "=r"(r[1]) : "r"(addr));
}
__device__ __forceinline__ void mma16816(float (&d)[4], const uint32_t (&a)[4],
                                         uint32_t b0, uint32_t b1) {
    asm volatile("mma.sync.aligned.m16n8k16.row.col.f32.bf16.bf16.f32 "
        "{%0,%1,%2,%3}, {%4,%5,%6,%7}, {%8,%9}, {%0,%1,%2,%3};"
        : "+f"(d[0]), "+f"(d[1]), "+f"(d[2]), "+f"(d[3])
        : "r"(a[0]), "r"(a[1]), "r"(a[2]), "r"(a[3]), "r"(b0), "r"(b1));
}
__device__ __forceinline__ void cvt_split2(float x, float y, uint32_t& hi, uint32_t& lo) {
    __nv_bfloat16 hx = __float2bfloat16(x), hy = __float2bfloat16(y);
    float rx = x - __bfloat162float(hx), ry = y - __bfloat162float(hy);
    __nv_bfloat162 h2; h2.x = hx; h2.y = hy;
    __nv_bfloat162 l2; l2.x = __float2bfloat16(rx); l2.y = __float2bfloat16(ry);
    hi = *(uint32_t*)&h2; lo = *(uint32_t*)&l2;
}

// ---------------- fp32 -> bf16 hi/lo split ----------------
__global__ __launch_bounds__(256) void conv_split_kernel(
    const float* __restrict__ x, __nv_bfloat16* __restrict__ hi,
    __nv_bfloat16* __restrict__ lo, int n4)
{
    int i = blockIdx.x * 256 + threadIdx.x;
    if (i >= n4) return;
    float4 v = ((const float4*)x)[i];
    uint32_t h0, l0, h1, l1;
    cvt_split2(v.x, v.y, h0, l0);
    cvt_split2(v.z, v.w, h1, l1);
    ((uint2*)hi)[i] = make_uint2(h0, h1);
    ((uint2*)lo)[i] = make_uint2(l0, l1);
}

// ---------------- mma.sync GEMM: C[4096,1024] = A @ W^T + bias ----------------
#define G_STRIDE_B   80
#define G_TILE_B     (128 * G_STRIDE_B)
#define G_STAGE_B    (4 * G_TILE_B)
#define G_SMEM_B     (2 * G_STAGE_B)
#define G_NC         (D_MODEL / 32)

__global__ __launch_bounds__(256) void gemm_mma_kernel(
    const __nv_bfloat16* __restrict__ Ah, const __nv_bfloat16* __restrict__ Al,
    const __nv_bfloat16* __restrict__ Wh, const __nv_bfloat16* __restrict__ Wl,
    const float* __restrict__ bias, float* __restrict__ C)
{
    extern __shared__ char smem[];
    const uint32_t sbase = smem_u32(smem);
    const int tid  = threadIdx.x;
    const int wid  = tid >> 5;
    const int lane = tid & 31;
    const int wm   = wid >> 2;
    const int wn   = wid & 3;
    const int m0 = blockIdx.y * 128;
    const int n0 = blockIdx.x * 128;

    const __nv_bfloat16* base[4] = {
        Ah + (size_t)m0 * D_MODEL, Al + (size_t)m0 * D_MODEL,
        Wh + (size_t)n0 * D_MODEL, Wl + (size_t)n0 * D_MODEL
    };

    float acc[4][4][4];
#pragma unroll
    for (int i = 0; i < 4; i++)
#pragma unroll
        for (int j = 0; j < 4; j++)
#pragma unroll
            for (int k = 0; k < 4; k++) acc[i][j][k] = 0.f;

    uint4 ldreg[8];
    auto ldg_chunk = [&](int c) {
#pragma unroll
        for (int it = 0; it < 8; it++) {
            int g   = tid + it * 256;
            int p   = g >> 9;
            int idx = g & 511;
            int row = idx >> 2;
            int ch  = idx & 3;
            ldreg[it] = *(const uint4*)(base[p] + (size_t)row * D_MODEL + c * 32 + ch * 8);
        }
    };
    auto sts_chunk = [&](int s) {
        char* dst = smem + s * G_STAGE_B;
#pragma unroll
        for (int it = 0; it < 8; it++) {
            int g   = tid + it * 256;
            int p   = g >> 9;
            int idx = g & 511;
            int row = idx >> 2;
            int ch  = idx & 3;
            *(uint4*)(dst + p * G_TILE_B + row * G_STRIDE_B + ch * 16) = ldreg[it];
        }
    };

    const int a_row = wm * 64 + (lane & 7) + ((lane >> 3) & 1) * 8;
    const int a_cho = (lane >> 4) & 1;
    const int b_row = wn * 32 + (lane & 7);
    const int b_cho = (lane >> 3) & 1;

    auto compute = [&](int s) {
        const uint32_t st  = sbase + s * G_STAGE_B;
        const uint32_t aHb = st + a_row * G_STRIDE_B + a_cho * 16;
        const uint32_t bHb = st + 2 * G_TILE_B + b_row * G_STRIDE_B + b_cho * 16;
#pragma unroll
        for (int ks = 0; ks < 2; ks++) {
            uint32_t aks = aHb + ks * 32;
            uint32_t bks = bHb + ks * 32;
            uint32_t aH[4][4], aL[4][4];
#pragma unroll
            for (int mi = 0; mi < 4; mi++) {
                ldsm_x4(aH[mi], aks + mi * (16 * G_STRIDE_B));
                ldsm_x4(aL[mi], aks + G_TILE_B + mi * (16 * G_STRIDE_B));
            }
#pragma unroll
            for (int ni = 0; ni < 4; ni++) {
                uint32_t bH[2], bL[2];
                ldsm_x2(bH, bks + ni * (8 * G_STRIDE_B));
                ldsm_x2(bL, bks + G_TILE_B + ni * (8 * G_STRIDE_B));
#pragma unroll
                for (int mi = 0; mi < 4; mi++) {
                    mma16816(acc[mi][ni], aH[mi], bH[0], bH[1]);
                    mma16816(acc[mi][ni], aH[mi], bL[0], bL[1]);
                    mma16816(acc[mi][ni], aL[mi], bH[0], bH[1]);
                }
            }
        }
    };

    ldg_chunk(0);
    sts_chunk(0);
    __syncthreads();
    for (int c = 0; c < G_NC; c++) {
        if (c + 1 < G_NC) ldg_chunk(c + 1);
        compute(c & 1);
        __syncthreads();
        if (c + 1 < G_NC) {
            sts_chunk((c + 1) & 1);
            __syncthreads();
        }
    }

    const int mb = m0 + wm * 64;
    const int nb = n0 + wn * 32;
    const int rl = lane >> 2;
    const int cl = 2 * (lane & 3);
#pragma unroll
    for (int ni = 0; ni < 4; ni++) {
        int cc = nb + ni * 8 + cl;
        float2 bv = *(const float2*)(bias + cc);
#pragma unroll
        for (int mi = 0; mi < 4; mi++) {
            int r0 = mb + mi * 16 + rl;
            float2 v0 = make_float2(acc[mi][ni][0] + bv.x, acc[mi][ni][1] + bv.y);
            float2 v1 = make_float2(acc[mi][ni][2] + bv.x, acc[mi][ni][3] + bv.y);
            *(float2*)(C + (size_t)r0 * D_MODEL + cc)       = v0;
            *(float2*)(C + (size_t)(r0 + 8) * D_MODEL + cc) = v1;
        }
    }
}

// ---------------------------------------------------------------------------
// mma.sync flash attention. Block: 128 q rows x one (b,h). 8 warps, m16 each.
// 64-key iterations; bf16 3-term split for QK and PV; fp32 softmax.
// Epilogue writes bf16 hi/lo directly to g_ah/g_al (input to Wo GEMM).
// ---------------------------------------------------------------------------
#define A_STRIDE  144                       // bytes per 64-elem bf16 row
#define A_QSZ     (128 * A_STRIDE)          // 18432 per Q part
#define A_KSZ     (64 * A_STRIDE)           // 9216 per K/V part
#define A_STAGE   (4 * A_KSZ + 512)         // Kh,Kl,Vh,Vl + mask
#define A_SMEM    (2 * A_QSZ + 2 * A_STAGE) // 111616
#define A_NITER   (T_SEQ / 64)

__global__ __launch_bounds__(256, 1) void attn_mma_kernel(const int* __restrict__ mask)
{
    extern __shared__ char smem[];
    const uint32_t sbase = smem_u32(smem);
    const int tid  = threadIdx.x;
    const int w    = tid >> 5;
    const int lane = tid & 31;
    const int qt   = blockIdx.x;            // 0..15 (128 q rows each)
    const int bh   = blockIdx.y;
    const int b    = bh >> 4;
    const int h    = bh & 15;

    const float* Qg = g_q + (size_t)(b * T_SEQ + qt * 128) * D_MODEL + h * 64;
    const float* Kg = g_k + (size_t)(b * T_SEQ) * D_MODEL + h * 64;
    const float* Vg = g_v + (size_t)(b * T_SEQ) * D_MODEL + h * 64;
    const int* mb = mask + b * T_SEQ;

    // ---- load Q tile (128x64 fp32), split to bf16 hi/lo in smem ----
#pragma unroll
    for (int i = 0; i < 8; i++) {
        int g = tid + i * 256;          // float4 index, 0..2047
        int row = g >> 4, ch = g & 15;
        float4 q = *(const float4*)(Qg + (size_t)row * D_MODEL + ch * 4);
        uint32_t h0, l0, h1, l1;
        cvt_split2(q.x, q.y, h0, l0);
        cvt_split2(q.z, q.w, h1, l1);
        *(uint2*)(smem + row * A_STRIDE + ch * 8)         = make_uint2(h0, h1);
        *(uint2*)(smem + A_QSZ + row * A_STRIDE + ch * 8) = make_uint2(l0, l1);
    }
    __syncthreads();

    // ---- per-warp Q fragments (kept in registers for the whole kernel) ----
    uint32_t Qh[4][4], Ql[4][4];
    {
        const int a_row = 16 * w + (lane & 7) + 8 * ((lane >> 3) & 1);
        const uint32_t abase = sbase + a_row * A_STRIDE + ((lane >> 4) & 1) * 16;
#pragma unroll
        for (int kf = 0; kf < 4; kf++) {
            ldsm_x4(Qh[kf], abase + kf * 32);
            ldsm_x4(Ql[kf], abase + A_QSZ + kf * 32);
        }
    }

    // ---- state ----
    float O[8][4];
#pragma unroll
    for (int i = 0; i < 8; i++)
#pragma unroll
        for (int j = 0; j < 4; j++) O[i][j] = 0.f;
    float m0r = -1e30f, m1r = -1e30f, l0r = 0.f, l1r = 0.f;

    // ---- K/V stage loaders (register-staged) ----
    uint32_t stg[32];
    float mreg = 0.f;
    auto ldg_stage = [&](int it) {
        const int s0 = it * 64;
        const float* Ks = Kg + (size_t)s0 * D_MODEL;
        const float* Vs = Vg + (size_t)s0 * D_MODEL;
#pragma unroll
        for (int i = 0; i < 4; i++) {
            int g = tid + i * 256;      // float4 idx 0..1023
            int row = g >> 4, ch = g & 15;
            float4 kv = *(const float4*)(Ks + (size_t)row * D_MODEL + ch * 4);
            float4 vv = *(const float4*)(Vs + (size_t)row * D_MODEL + ch * 4);
            cvt_split2(kv.x, kv.y, stg[2 * i], stg[8 + 2 * i]);
            cvt_split2(kv.z, kv.w, stg[2 * i + 1], stg[8 + 2 * i + 1]);
            cvt_split2(vv.x, vv.y, stg[16 + 2 * i], stg[24 + 2 * i]);
            cvt_split2(vv.z, vv.w, stg[16 + 2 * i + 1], stg[24 + 2 * i + 1]);
        }
        if (tid < 64) mreg = (mb[s0 + tid] != 0) ? 1.0f : 0.0f;
    };
    auto sts_stage = [&](int s) {
        char* bs = smem + 2 * A_QSZ + s * A_STAGE;
#pragma unroll
        for (int i = 0; i < 4; i++) {
            int g = tid + i * 256;
            int row = g >> 4, ch = g & 15;
            size_t off = (size_t)row * A_STRIDE + ch * 8;
            *(uint2*)(bs + off)             = make_uint2(stg[2 * i], stg[2 * i + 1]);
            *(uint2*)(bs + A_KSZ + off)     = make_uint2(stg[8 + 2 * i], stg[8 + 2 * i + 1]);
            *(uint2*)(bs + 2 * A_KSZ + off) = make_uint2(stg[16 + 2 * i], stg[16 + 2 * i + 1]);
            *(uint2*)(bs + 3 * A_KSZ + off) = make_uint2(stg[24 + 2 * i], stg[24 + 2 * i + 1]);
        }
        if (tid < 64) *(float*)(bs + 4 * A_KSZ + tid * 4) = mreg;
    };

    ldg_stage(0);
    sts_stage(0);
    __syncthreads();

    const float SCALE = 0.125f;

    for (int it = 0; it < A_NITER; it++) {
        if (it + 1 < A_NITER) ldg_stage(it + 1);

        const uint32_t stb = sbase + 2 * A_QSZ + (it & 1) * A_STAGE;
        const uint32_t kb  = stb;
        const uint32_t vb  = stb + 2 * A_KSZ;
        const uint32_t mbx = stb + 4 * A_KSZ;

        // ---- S = Q K^T (3-term split) ----
        float S[8][4];
#pragma unroll
        for (int i = 0; i < 8; i++)
#pragma unroll
            for (int j = 0; j < 4; j++) S[i][j] = 0.f;

        {
            const uint32_t kaddr0 = kb + (lane & 7) * A_STRIDE + (lane >> 3) * 16;
#pragma unroll
            for (int kp = 0; kp < 2; kp++) {
#pragma unroll
                for (int nf = 0; nf < 8; nf++) {
                    uint32_t bh4[4], bl4[4];
                    uint32_t addr = kaddr0 + nf * (8 * A_STRIDE) + kp * 64;
                    ldsm_x4(bh4, addr);
                    ldsm_x4(bl4, addr + A_KSZ);
                    mma16816(S[nf], Qh[2 * kp],     bh4[0], bh4[1]);
                    mma16816(S[nf], Qh[2 * kp],     bl4[0], bl4[1]);
                    mma16816(S[nf], Ql[2 * kp],     bh4[0], bh4[1]);
                    mma16816(S[nf], Qh[2 * kp + 1], bh4[2], bh4[3]);
                    mma16816(S[nf], Qh[2 * kp + 1], bl4[2], bl4[3]);
                    mma16816(S[nf], Ql[2 * kp + 1], bh4[2], bh4[3]);
                }
            }
        }

        // ---- softmax (fp32, online) ----
        float mx0 = -1e30f, mx1 = -1e30f;
        float mkx[8], mky[8];
#pragma unroll
        for (int f = 0; f < 8; f++) {
            float2 mk = *(float2*)(smem + (mbx - sbase) + (8 * f + 2 * (lane & 3)) * 4);
            mkx[f] = mk.x; mky[f] = mk.y;
            S[f][0] = (mk.x > 0.f) ? S[f][0] * SCALE : -1e30f;
            S[f][1] = (mk.y > 0.f) ? S[f][1] * SCALE : -1e30f;
            S[f][2] = (mk.x > 0.f) ? S[f][2] * SCALE : -1e30f;
            S[f][3] = (mk.y > 0.f) ? S[f][3] * SCALE : -1e30f;
            mx0 = fmaxf(mx0, fmaxf(S[f][0], S[f][1]));
            mx1 = fmaxf(mx1, fmaxf(S[f][2], S[f][3]));
        }
        mx0 = fmaxf(mx0, __shfl_xor_sync(0xffffffffu, mx0, 1));
        mx0 = fmaxf(mx0, __shfl_xor_sync(0xffffffffu, mx0, 2));
        mx1 = fmaxf(mx1, __shfl_xor_sync(0xffffffffu, mx1, 1));
        mx1 = fmaxf(mx1, __shfl_xor_sync(0xffffffffu, mx1, 2));

        float mn0 = fmaxf(m0r, mx0), mn1 = fmaxf(m1r, mx1);
        float c0 = __expf(m0r - mn0), c1 = __expf(m1r - mn1);

        uint32_t Ph[4][4], Pl[4][4];
        float rs0 = 0.f, rs1 = 0.f;
#pragma unroll
        for (int f = 0; f < 8; f++) {
            float p0 = __expf(S[f][0] - mn0) * mkx[f];
            float p1 = __expf(S[f][1] - mn0) * mky[f];
            float p2 = __expf(S[f][2] - mn1) * mkx[f];
            float p3 = __expf(S[f][3] - mn1) * mky[f];
            rs0 += p0 + p1;
            rs1 += p2 + p3;
            uint32_t h01, l01, h23, l23;
            cvt_split2(p0, p1, h01, l01);
            cvt_split2(p2, p3, h23, l23);
            int kf = f >> 1, half = (f & 1) * 2;
            Ph[kf][half]     = h01;  Ph[kf][half + 1] = h23;
            Pl[kf][half]     = l01;  Pl[kf][half + 1] = l23;
        }
        rs0 += __shfl_xor_sync(0xffffffffu, rs0, 1);
        rs0 += __shfl_xor_sync(0xffffffffu, rs0, 2);
        rs1 += __shfl_xor_sync(0xffffffffu, rs1, 1);
        rs1 += __shfl_xor_sync(0xffffffffu, rs1, 2);

        l0r = l0r * c0 + rs0;  m0r = mn0;
        l1r = l1r * c1 + rs1;  m1r = mn1;
#pragma unroll
        for (int i = 0; i < 8; i++) {
            O[i][0] *= c0; O[i][1] *= c0;
            O[i][2] *= c1; O[i][3] *= c1;
        }

        // ---- O += P V (3-term split; V via trans ldmatrix) ----
        {
            const uint32_t vaddr0 = vb + ((lane & 7) + 8 * ((lane >> 3) & 1)) * A_STRIDE
                                       + (lane >> 4) * 16;
#pragma unroll
            for (int np = 0; np < 4; np++) {
#pragma unroll
                for (int kf = 0; kf < 4; kf++) {
                    uint32_t bh4[4], bl4[4];
                    uint32_t addr = vaddr0 + kf * (16 * A_STRIDE) + np * 32;
                    ldsm_x4t(bh4, addr);
                    ldsm_x4t(bl4, addr + A_KSZ);
                    mma16816(O[2 * np],     Ph[kf], bh4[0], bh4[1]);
                    mma16816(O[2 * np],     Ph[kf], bl4[0], bl4[1]);
                    mma16816(O[2 * np],     Pl[kf], bh4[0], bh4[1]);
                    mma16816(O[2 * np + 1], Ph[kf], bh4[2], bh4[3]);
                    mma16816(O[2 * np + 1], Ph[kf], bl4[2], bl4[3]);
                    mma16816(O[2 * np + 1], Pl[kf], bh4[2], bh4[3]);
                }
            }
        }

        if (it + 1 < A_NITER) sts_stage((it + 1) & 1);
        __syncthreads();
    }

    // ---- epilogue: normalize, split to bf16 hi/lo, write g_ah/g_al ----
    const float inv0 = (l0r > 0.f) ? (1.0f / l0r) : 0.f;
    const float inv1 = (l1r > 0.f) ? (1.0f / l1r) : 0.f;
    const int grow0 = b * T_SEQ + qt * 128 + 16 * w + (lane >> 2);
    const int colb  = h * 64 + 2 * (lane & 3);
#pragma unroll
    for (int nf = 0; nf < 8; nf++) {
        int col = colb + nf * 8;
        uint32_t h01, l01, h23, l23;
        cvt_split2(O[nf][0] * inv0, O[nf][1] * inv0, h01, l01);
        cvt_split2(O[nf][2] * inv1, O[nf][3] * inv1, h23, l23);
        *(uint32_t*)(g_ah + (size_t)grow0 * D_MODEL + col)       = h01;
        *(uint32_t*)(g_al + (size_t)grow0 * D_MODEL + col)       = l01;
        *(uint32_t*)(g_ah + (size_t)(grow0 + 8) * D_MODEL + col) = h23;
        *(uint32_t*)(g_al + (size_t)(grow0 + 8) * D_MODEL + col) = l23;
    }
}

// ---------------------------------------------------------------------------
extern "C" void kernel_launch(void* const* d_in, const int* in_sizes, int n_in,
                              void* d_out, int out_size)
{
    const float* query = (const float*)d_in[0];
    const float* key   = (const float*)d_in[1];
    const float* value = (const float*)d_in[2];
    const int*   mask  = (const int*)d_in[3];
    const float* Wq = (const float*)d_in[4];
    const float* bq = (const float*)d_in[5];
    const float* Wk = (const float*)d_in[6];
    const float* bk = (const float*)d_in[7];
    const float* Wv = (const float*)d_in[8];
    const float* bv = (const float*)d_in[9];
    const float* Wo = (const float*)d_in[10];
    const float* bo = (const float*)d_in[11];
    float* out = (float*)d_out;

    float *gq, *gk, *gv;
    __nv_bfloat16 *ah, *al, *wh, *wl;
    cudaGetSymbolAddress((void**)&gq, g_q);
    cudaGetSymbolAddress((void**)&gk, g_k);
    cudaGetSymbolAddress((void**)&gv, g_v);
    cudaGetSymbolAddress((void**)&ah, g_ah);
    cudaGetSymbolAddress((void**)&al, g_al);
    cudaGetSymbolAddress((void**)&wh, g_wh);
    cudaGetSymbolAddress((void**)&wl, g_wl);

    cudaFuncSetAttribute(gemm_mma_kernel, cudaFuncAttributeMaxDynamicSharedMemorySize, G_SMEM_B);
    cudaFuncSetAttribute(attn_mma_kernel, cudaFuncAttributeMaxDynamicSharedMemorySize, A_SMEM);

    const int nact4 = M_ROWS * D_MODEL / 4;
    const int nw4   = D_MODEL * D_MODEL / 4;
    dim3 cga(nact4 / 256), cgw(nw4 / 256);
    dim3 ggrid(D_MODEL / 128, M_ROWS / 128);

    // Q projection
    conv_split_kernel<<<cga, 256>>>(query, ah, al, nact4);
    conv_split_kernel<<<cgw, 256>>>(Wq, wh, wl, nw4);
    gemm_mma_kernel<<<ggrid, 256, G_SMEM_B>>>(ah, al, wh, wl, bq, gq);
    // K projection
    conv_split_kernel<<<cga, 256>>>(key, ah, al, nact4);
    conv_split_kernel<<<cgw, 256>>>(Wk, wh, wl, nw4);
    gemm_mma_kernel<<<ggrid, 256, G_SMEM_B>>>(ah, al, wh, wl, bk, gk);
    // V projection
    conv_split_kernel<<<cga, 256>>>(value, ah, al, nact4);
    conv_split_kernel<<<cgw, 256>>>(Wv, wh, wl, nw4);
    gemm_mma_kernel<<<ggrid, 256, G_SMEM_B>>>(ah, al, wh, wl, bv, gv);

    // attention (writes split bf16 activations for Wo directly)
    dim3 agrid(T_SEQ / 128, B_BATCH * H_HEADS);   // (16, 32)
    attn_mma_kernel<<<agrid, 256, A_SMEM>>>(mask);

    // output projection
    conv_split_kernel<<<cgw, 256>>>(Wo, wh, wl, nw4);
    gemm_mma_kernel<<<ggrid, 256, G_SMEM_B>>>(ah, al, wh, wl, bo, out);
}